// round 8
// baseline (speedup 1.0000x reference)
#include <cuda_runtime.h>
#include <cuda_bf16.h>
#include <cstdint>

// KPConv as warp-MMA GEMM with REGISTER-DIRECT A fragments:
//   A[p, j] = exp(-0.5*d2(p,k)/sigma^2) * x[p,i]  (j=3k+i, 48 cols = 3 k-tiles)
//   out = A @ W.  fp32 via bf16 split: D = Ah*Wh + Al*Wh + Ah*Wl.
// Each lane computes exactly its m16n8k16 A-fragment values in registers
// (rows gid, gid+8; cols 2*tig+{0,1,8,9}+16kt) -> no smem A, no ldmatrix,
// no barriers. Warp owns a 16-row tile with all 64 output cols.

#define KP_    16
#define JDIM   48
#define COUT_  64
#define NTHR   128

__device__ __forceinline__ uint32_t pack_bf_rn(float lo, float hi) {
    uint32_t r;
    asm("cvt.rn.bf16x2.f32 %0, %1, %2;" : "=r"(r) : "f"(hi), "f"(lo));
    return r;
}
__device__ __forceinline__ uint32_t pack_hi_trunc(float ae, float ao) {
    uint32_t r;
    asm("prmt.b32 %0, %1, %2, 0x7632;" : "=r"(r) : "r"(__float_as_uint(ae)), "r"(__float_as_uint(ao)));
    return r;
}
__device__ __forceinline__ float trunc_bf(float a) {
    return __uint_as_float(__float_as_uint(a) & 0xFFFF0000u);
}
__device__ __forceinline__ float ex2f(float a) {
    float r;
    asm("ex2.approx.f32 %0, %1;" : "=f"(r) : "f"(a));
    return r;
}
__device__ __forceinline__ void mma_bf16(float* c, const uint32_t* a, const uint32_t* b) {
    asm volatile(
        "mma.sync.aligned.m16n8k16.row.col.f32.bf16.bf16.f32 "
        "{%0,%1,%2,%3}, {%4,%5,%6,%7}, {%8,%9}, {%0,%1,%2,%3};"
        : "+f"(c[0]), "+f"(c[1]), "+f"(c[2]), "+f"(c[3])
        : "r"(a[0]), "r"(a[1]), "r"(a[2]), "r"(a[3]), "r"(b[0]), "r"(b[1]));
}

__global__ __launch_bounds__(NTHR, 3)
void kpconv_direct_kernel(const float* __restrict__ x,
                          const float* __restrict__ kpts,
                          const float* __restrict__ wts,
                          const float* __restrict__ sigma,
                          float* __restrict__ out,
                          int npts)
{
    __shared__ float  sW[JDIM * COUT_];     // W staging (persists; only B-frag build reads it)
    __shared__ float4 sKP4[KP_];            // padded kernel points for LDS.128

    const int tid  = threadIdx.x;
    const int wid  = tid >> 5;
    const int lane = tid & 31;
    const int gid  = lane >> 2;     // 0..7  (fragment row group)
    const int tig  = lane & 3;      // 0..3  (fragment col group)

    if (tid < KP_)
        sKP4[tid] = make_float4(kpts[3 * tid], kpts[3 * tid + 1], kpts[3 * tid + 2], 0.f);
    for (int i = tid; i < JDIM * COUT_; i += NTHR) sW[i] = wts[i];
    __syncthreads();

    // ---- B fragments (hi/lo bf16), lane-resident: 96 regs ----
    uint32_t Bh[8][3][2], Bl[8][3][2];
#pragma unroll
    for (int nt = 0; nt < 8; nt++) {
#pragma unroll
        for (int kt = 0; kt < 3; kt++) {
            int n  = nt * 8 + gid;
            int j0 = kt * 16 + 2 * tig;
#pragma unroll
            for (int h = 0; h < 2; h++) {
                float w0 = sW[(j0 + 8 * h    ) * COUT_ + n];
                float w1 = sW[(j0 + 8 * h + 1) * COUT_ + n];
                float h0 = __bfloat162float(__float2bfloat16_rn(w0));
                float h1 = __bfloat162float(__float2bfloat16_rn(w1));
                Bh[nt][kt][h] = pack_bf_rn(h0, h1);
                Bl[nt][kt][h] = pack_bf_rn(w0 - h0, w1 - h1);
            }
        }
    }

    const float sg  = sigma[0];
    const float cc2 = -0.72134752f / (sg * sg);   // -0.5*log2(e)/sigma^2

    const int ntiles   = (npts + 15) >> 4;
    const int warpGlob = blockIdx.x * 4 + wid;
    const int numWarps = gridDim.x * 4;
    const int jbase    = 2 * tig;

    for (int t = warpGlob; t < ntiles; t += numWarps) {
        const int base = t << 4;
        const int rowA = base + gid;
        const int rowB = rowA + 8;

        float xa0 = 0.f, xa1 = 0.f, xa2 = 0.f, xb0 = 0.f, xb1 = 0.f, xb2 = 0.f;
        if (rowA < npts) { xa0 = x[3 * rowA]; xa1 = x[3 * rowA + 1]; xa2 = x[3 * rowA + 2]; }
        if (rowB < npts) { xb0 = x[3 * rowB]; xb1 = x[3 * rowB + 1]; xb2 = x[3 * rowB + 2]; }

        float acc[8][4];
#pragma unroll
        for (int nt = 0; nt < 8; nt++)
#pragma unroll
            for (int c = 0; c < 4; c++) acc[nt][c] = 0.f;

#pragma unroll
        for (int kt = 0; kt < 3; kt++) {
            // ---- compute this lane's A fragment values directly ----
            float vA[4], vB[4];
#pragma unroll
            for (int s = 0; s < 4; s++) {
                const int off = (s & 1) + (s >> 1) * 8;        // {0,1,8,9}
                const int j   = kt * 16 + jbase + off;
                const int k   = (j * 21846) >> 16;             // j / 3
                const int i3  = j - 3 * k;                     // j % 3
                const float4 kp = sKP4[k];
                // row A
                float dxa = xa0 - kp.x, dya = xa1 - kp.y, dza = xa2 - kp.z;
                float d2a = fmaf(dxa, dxa, fmaf(dya, dya, dza * dza));
                float ga  = ex2f(cc2 * d2a);
                float xia = (i3 == 0) ? xa0 : ((i3 == 1) ? xa1 : xa2);
                vA[s] = ga * xia;
                // row B
                float dxb = xb0 - kp.x, dyb = xb1 - kp.y, dzb = xb2 - kp.z;
                float d2b = fmaf(dxb, dxb, fmaf(dyb, dyb, dzb * dzb));
                float gb  = ex2f(cc2 * d2b);
                float xib = (i3 == 0) ? xb0 : ((i3 == 1) ? xb1 : xb2);
                vB[s] = gb * xib;
            }
            uint32_t ah[4], al[4];
            ah[0] = pack_hi_trunc(vA[0], vA[1]);
            ah[1] = pack_hi_trunc(vB[0], vB[1]);
            ah[2] = pack_hi_trunc(vA[2], vA[3]);
            ah[3] = pack_hi_trunc(vB[2], vB[3]);
            al[0] = pack_bf_rn(vA[0] - trunc_bf(vA[0]), vA[1] - trunc_bf(vA[1]));
            al[1] = pack_bf_rn(vB[0] - trunc_bf(vB[0]), vB[1] - trunc_bf(vB[1]));
            al[2] = pack_bf_rn(vA[2] - trunc_bf(vA[2]), vA[3] - trunc_bf(vA[3]));
            al[3] = pack_bf_rn(vB[2] - trunc_bf(vB[2]), vB[3] - trunc_bf(vB[3]));

#pragma unroll
            for (int nt = 0; nt < 8; nt++) mma_bf16(acc[nt], ah, Bh[nt][kt]);
#pragma unroll
            for (int nt = 0; nt < 8; nt++) mma_bf16(acc[nt], al, Bh[nt][kt]);
#pragma unroll
            for (int nt = 0; nt < 8; nt++) mma_bf16(acc[nt], ah, Bl[nt][kt]);
        }

        // ---- epilogue: butterfly (xor 1) -> float4 -> STG.128 (64B/row runs) ----
        const int rowLo = rowA;
        const int rowHi = rowB;
        const bool ev   = (tig & 1) == 0;
#pragma unroll
        for (int ntp = 0; ntp < 4; ntp++) {
            const int ntA = 2 * ntp, ntB = ntA + 1;
            const int col = ev ? (16 * ntp + 2 * tig) : (16 * ntp + 8 + 2 * (tig - 1));
#pragma unroll
            for (int hseg = 0; hseg < 2; hseg++) {
                float m0 = acc[ntA][2 * hseg], m1 = acc[ntA][2 * hseg + 1];
                float b0 = acc[ntB][2 * hseg], b1 = acc[ntB][2 * hseg + 1];
                float s0 = ev ? b0 : m0;
                float s1 = ev ? b1 : m1;
                float r0 = __shfl_xor_sync(0xFFFFFFFFu, s0, 1);
                float r1 = __shfl_xor_sync(0xFFFFFFFFu, s1, 1);
                float4 v;
                if (ev) v = make_float4(m0, m1, r0, r1);
                else    v = make_float4(r0, r1, b0, b1);
                const int row = hseg ? rowHi : rowLo;
                if (row < npts)
                    *reinterpret_cast<float4*>(out + (size_t)row * COUT_ + col) = v;
            }
        }
    }
}

extern "C" void kernel_launch(void* const* d_in, const int* in_sizes, int n_in,
                              void* d_out, int out_size)
{
    const float *x = nullptr, *kp = nullptr, *wt = nullptr, *sg = nullptr;
    int x_elems = 0;
    for (int i = 0; i < n_in; i++) {
        int s = in_sizes[i];
        if (s == 1)                    sg = (const float*)d_in[i];
        else if (s == JDIM)            kp = (const float*)d_in[i];
        else if (s == KP_ * 3 * COUT_) wt = (const float*)d_in[i];
        else { x = (const float*)d_in[i]; x_elems = s; }
    }
    const int npts   = x_elems / 3;
    const int ntiles = (npts + 15) >> 4;
    int grid = 148 * 3;
    int maxg = (ntiles + 3) / 4;
    if (grid > maxg) grid = maxg;

    kpconv_direct_kernel<<<grid, NTHR>>>(x, kp, wt, sg, (float*)d_out, npts);
}

// round 9
// speedup vs baseline: 1.0689x; 1.0689x over previous
#include <cuda_runtime.h>
#include <cuda_fp16.h>
#include <cstdint>

// KPConv as warp-MMA GEMM, warp-independent m-split tiles, fp16 2-pass:
//   A[p, j] = exp(-0.5*d2(p,k)/sigma^2) * x[p,i]  (j=3k+i, 48 cols = 3 k-tiles)
//   out = A @ W.  fp32 via fp16 A-split, W rounded once:
//   D = Ah*Wh + Al*Wh   (error = a*(w - wh) ~ 2^-12 per term, rel_err ~1e-4)
// Each warp owns a 16-row tile x all 64 cols. No block/pair barriers.

#define KP_    16
#define JDIM   48
#define COUT_  64
#define NTHR   128
#define ROWB   112                    // fp16 A row stride bytes (96 data + pad)
#define AWARP  (16 * ROWB)            // 1792 B per (warp, half)

__device__ __forceinline__ uint32_t smem_u32(const void* p) {
    uint32_t a;
    asm("{ .reg .u64 t; cvta.to.shared.u64 t, %1; cvt.u32.u64 %0, t; }" : "=r"(a) : "l"(p));
    return a;
}
__device__ __forceinline__ uint32_t pack_h_rn(float lo, float hi) {
    uint32_t r;
    asm("cvt.rn.f16x2.f32 %0, %1, %2;" : "=r"(r) : "f"(hi), "f"(lo));
    return r;
}
__device__ __forceinline__ void ldsm_x4(uint32_t* r, uint32_t addr) {
    asm volatile("ldmatrix.sync.aligned.m8n8.x4.shared.b16 {%0,%1,%2,%3}, [%4];"
                 : "=r"(r[0]), "=r"(r[1]), "=r"(r[2]), "=r"(r[3]) : "r"(addr));
}
__device__ __forceinline__ void mma_f16(float* c, const uint32_t* a, const uint32_t* b) {
    asm volatile(
        "mma.sync.aligned.m16n8k16.row.col.f32.f16.f16.f32 "
        "{%0,%1,%2,%3}, {%4,%5,%6,%7}, {%8,%9}, {%0,%1,%2,%3};"
        : "+f"(c[0]), "+f"(c[1]), "+f"(c[2]), "+f"(c[3])
        : "r"(a[0]), "r"(a[1]), "r"(a[2]), "r"(a[3]), "r"(b[0]), "r"(b[1]));
}
__device__ __forceinline__ float ex2f(float a) {
    float r;
    asm("ex2.approx.f32 %0, %1;" : "=f"(r) : "f"(a));
    return r;
}

__global__ __launch_bounds__(NTHR, 4)
void kpconv_f16_kernel(const float* __restrict__ x,
                       const float* __restrict__ kpts,
                       const float* __restrict__ wts,
                       const float* __restrict__ sigma,
                       float* __restrict__ out,
                       int npts)
{
    // per-warp A staging: [warp][hi/lo][16 rows x 112B] = 14336 B; W staged aliased.
    __shared__ __align__(16) char sA[4][2][AWARP];
    __shared__ float4 sKP4[KP_];

    const int tid  = threadIdx.x;
    const int wid  = tid >> 5;
    const int lane = tid & 31;
    const int gid  = lane >> 2;     // 0..7
    const int tig  = lane & 3;      // 0..3

    if (tid < KP_)
        sKP4[tid] = make_float4(kpts[3 * tid], kpts[3 * tid + 1], kpts[3 * tid + 2], 0.f);

    // ---- one-time: stage W (aliased into sA), build fp16 B fragments ----
    float* sWf = reinterpret_cast<float*>(&sA[0][0][0]);   // 12288 <= 14336
    for (int i = tid; i < JDIM * COUT_; i += NTHR) sWf[i] = wts[i];
    __syncthreads();

    uint32_t Bh[8][3][2];
#pragma unroll
    for (int nt = 0; nt < 8; nt++) {
#pragma unroll
        for (int kt = 0; kt < 3; kt++) {
            int n  = nt * 8 + gid;
            int j0 = kt * 16 + 2 * tig;
#pragma unroll
            for (int h = 0; h < 2; h++) {
                float w0 = sWf[(j0 + 8 * h    ) * COUT_ + n];
                float w1 = sWf[(j0 + 8 * h + 1) * COUT_ + n];
                Bh[nt][kt][h] = pack_h_rn(w0, w1);
            }
        }
    }
    __syncthreads();   // W staging dead; sA belongs to warps now

    const float sg  = sigma[0];
    const float cc2 = -0.72134752f / (sg * sg);   // -0.5*log2(e)/sigma^2

    const uint32_t aHi = smem_u32(&sA[wid][0][0]);
    const uint32_t aLo = smem_u32(&sA[wid][1][0]);
    const uint32_t lmoff = (uint32_t)(lane & 15) * ROWB + (uint32_t)(lane >> 4) * 16;

    const int ntiles   = (npts + 15) >> 4;
    const int warpGlob = blockIdx.x * 4 + wid;
    const int numWarps = gridDim.x * 4;

    for (int t = warpGlob; t < ntiles; t += numWarps) {
        const int base = t << 4;

        // ---- phase 1: lane (r = lane>>1) computes k-half (lane&1) of row r ----
        {
            const int r  = lane >> 1;
            const int kh = lane & 1;          // k-half: k in [8*kh, 8*kh+8)
            const int p  = base + r;
            float x0 = 0.f, x1 = 0.f, x2 = 0.f;
            if (p < npts) { x0 = x[3 * p]; x1 = x[3 * p + 1]; x2 = x[3 * p + 2]; }
            float a[24];
#pragma unroll
            for (int kk = 0; kk < 8; kk++) {
                const float4 kp = sKP4[8 * kh + kk];
                float dx = x0 - kp.x, dy = x1 - kp.y, dz = x2 - kp.z;
                float d2 = fmaf(dx, dx, fmaf(dy, dy, dz * dz));
                float g  = ex2f(cc2 * d2);
                a[3 * kk] = g * x0; a[3 * kk + 1] = g * x1; a[3 * kk + 2] = g * x2;
            }
            uint32_t hv[12], lv[12];
#pragma unroll
            for (int m = 0; m < 12; m++) {
                float a0 = a[2 * m], a1 = a[2 * m + 1];
                uint32_t hp = pack_h_rn(a0, a1);
                __half2 h2 = *reinterpret_cast<__half2*>(&hp);
                float l0 = a0 - __low2float(h2);
                float l1 = a1 - __high2float(h2);
                hv[m] = hp;
                lv[m] = pack_h_rn(l0, l1);
            }
            char* rh = &sA[wid][0][0] + r * ROWB + kh * 48;
            char* rl = &sA[wid][1][0] + r * ROWB + kh * 48;
#pragma unroll
            for (int q = 0; q < 3; q++) {
                *reinterpret_cast<uint4*>(rh + q * 16) =
                    make_uint4(hv[4 * q], hv[4 * q + 1], hv[4 * q + 2], hv[4 * q + 3]);
                *reinterpret_cast<uint4*>(rl + q * 16) =
                    make_uint4(lv[4 * q], lv[4 * q + 1], lv[4 * q + 2], lv[4 * q + 3]);
            }
        }
        __syncwarp();

        // ---- phase 2: 3 k-tiles x 2 passes x 8 n-tiles ----
        float acc[8][4];
#pragma unroll
        for (int nt = 0; nt < 8; nt++)
#pragma unroll
            for (int c = 0; c < 4; c++) acc[nt][c] = 0.f;

#pragma unroll
        for (int kt = 0; kt < 3; kt++) {
            uint32_t ah[4], al[4];
            ldsm_x4(ah, aHi + lmoff + kt * 32);
            ldsm_x4(al, aLo + lmoff + kt * 32);
#pragma unroll
            for (int nt = 0; nt < 8; nt++) mma_f16(acc[nt], ah, Bh[nt][kt]);
#pragma unroll
            for (int nt = 0; nt < 8; nt++) mma_f16(acc[nt], al, Bh[nt][kt]);
        }

        // ---- epilogue: butterfly (xor 1) -> float4 -> STG.128 ----
        const int rowLo = base + gid;
        const int rowHi = rowLo + 8;
        const bool ev   = (tig & 1) == 0;
#pragma unroll
        for (int ntp = 0; ntp < 4; ntp++) {
            const int ntA = 2 * ntp, ntB = ntA + 1;
            const int col = ev ? (16 * ntp + 2 * tig) : (16 * ntp + 8 + 2 * (tig - 1));
#pragma unroll
            for (int hseg = 0; hseg < 2; hseg++) {
                float m0 = acc[ntA][2 * hseg], m1 = acc[ntA][2 * hseg + 1];
                float b0 = acc[ntB][2 * hseg], b1 = acc[ntB][2 * hseg + 1];
                float s0 = ev ? b0 : m0;
                float s1 = ev ? b1 : m1;
                float r0 = __shfl_xor_sync(0xFFFFFFFFu, s0, 1);
                float r1 = __shfl_xor_sync(0xFFFFFFFFu, s1, 1);
                float4 v;
                if (ev) v = make_float4(m0, m1, r0, r1);
                else    v = make_float4(r0, r1, b0, b1);
                const int row = hseg ? rowHi : rowLo;
                if (row < npts)
                    *reinterpret_cast<float4*>(out + (size_t)row * COUT_ + col) = v;
            }
        }
        __syncwarp();   // A tile consumed before next iteration overwrites it
    }
}

extern "C" void kernel_launch(void* const* d_in, const int* in_sizes, int n_in,
                              void* d_out, int out_size)
{
    const float *x = nullptr, *kp = nullptr, *wt = nullptr, *sg = nullptr;
    int x_elems = 0;
    for (int i = 0; i < n_in; i++) {
        int s = in_sizes[i];
        if (s == 1)                    sg = (const float*)d_in[i];
        else if (s == JDIM)            kp = (const float*)d_in[i];
        else if (s == KP_ * 3 * COUT_) wt = (const float*)d_in[i];
        else { x = (const float*)d_in[i]; x_elems = s; }
    }
    const int npts   = x_elems / 3;
    const int ntiles = (npts + 15) >> 4;
    int grid = 148 * 4;
    int maxg = (ntiles + 3) / 4;
    if (grid > maxg) grid = maxg;

    kpconv_f16_kernel<<<grid, NTHR>>>(x, kp, wt, sg, (float*)d_out, npts);
}

// round 10
// speedup vs baseline: 1.3956x; 1.3057x over previous
#include <cuda_runtime.h>
#include <cuda_fp16.h>
#include <cstdint>

// KPConv as warp-MMA GEMM: R6 pair-split structure + fp16 2-pass + LDG prefetch.
//   A[p, j] = exp(-0.5*d2(p,k)/sigma^2) * x[p,i]  (j=3k+i, 48 cols = 3 k-tiles)
//   out = A @ W.  fp32 via fp16 A-split, W rounded once: D = Ah*Wh + Al*Wh.
// A pair of warps owns a 32-row group: each warp builds its 16-row A tile
// (hi/lo fp16, stride 144B), then computes its 32-col n-half of BOTH tiles.
// Double-buffered A; one named bar.sync(64) per iteration. x prefetched.

#define KP_    16
#define JDIM   48
#define COUT_  64
#define NTHR   128
#define ROWB   144
#define AWARP  (16 * ROWB)   // 2304 B per (warp, half)

__device__ __forceinline__ uint32_t smem_u32(const void* p) {
    uint32_t a;
    asm("{ .reg .u64 t; cvta.to.shared.u64 t, %1; cvt.u32.u64 %0, t; }" : "=r"(a) : "l"(p));
    return a;
}
__device__ __forceinline__ uint32_t pack_h_rn(float lo, float hi) {
    uint32_t r;
    asm("cvt.rn.f16x2.f32 %0, %1, %2;" : "=r"(r) : "f"(hi), "f"(lo));
    return r;
}
__device__ __forceinline__ void ldsm_x4(uint32_t* r, uint32_t addr) {
    asm volatile("ldmatrix.sync.aligned.m8n8.x4.shared.b16 {%0,%1,%2,%3}, [%4];"
                 : "=r"(r[0]), "=r"(r[1]), "=r"(r[2]), "=r"(r[3]) : "r"(addr));
}
__device__ __forceinline__ void mma_f16(float* c, const uint32_t* a, const uint32_t* b) {
    asm volatile(
        "mma.sync.aligned.m16n8k16.row.col.f32.f16.f16.f32 "
        "{%0,%1,%2,%3}, {%4,%5,%6,%7}, {%8,%9}, {%0,%1,%2,%3};"
        : "+f"(c[0]), "+f"(c[1]), "+f"(c[2]), "+f"(c[3])
        : "r"(a[0]), "r"(a[1]), "r"(a[2]), "r"(a[3]), "r"(b[0]), "r"(b[1]));
}
__device__ __forceinline__ float ex2f(float a) {
    float r;
    asm("ex2.approx.f32 %0, %1;" : "=f"(r) : "f"(a));
    return r;
}
__device__ __forceinline__ void bar_pair(int id) {
    asm volatile("bar.sync %0, 64;" :: "r"(id) : "memory");
}

__global__ __launch_bounds__(NTHR, 5)
void kpconv_f16p_kernel(const float* __restrict__ x,
                        const float* __restrict__ kpts,
                        const float* __restrict__ wts,
                        const float* __restrict__ sigma,
                        float* __restrict__ out,
                        int npts)
{
    // [buf][warp][hi/lo][16 rows x 144B] = 36864 B; W (12288B) staged aliased.
    __shared__ __align__(16) char sA[2][4][2][AWARP];
    __shared__ float4 sKP4[KP_];

    const int tid  = threadIdx.x;
    const int wid  = tid >> 5;
    const int lane = tid & 31;
    const int gid  = lane >> 2;     // 0..7
    const int tig  = lane & 3;      // 0..3
    const int pr   = wid >> 1;      // pair id 0/1
    const int j    = wid & 1;       // n-half within pair
    const int colbase = 32 * j;

    if (tid < KP_)
        sKP4[tid] = make_float4(kpts[3 * tid], kpts[3 * tid + 1], kpts[3 * tid + 2], 0.f);

    // ---- one-time: stage W (aliased into sA), build this lane's fp16 B frags ----
    float* sWf = reinterpret_cast<float*>(&sA[0][0][0][0]);
    for (int i = tid; i < JDIM * COUT_; i += NTHR) sWf[i] = wts[i];
    __syncthreads();

    uint32_t B[4][3][2];
#pragma unroll
    for (int nt = 0; nt < 4; nt++) {
#pragma unroll
        for (int kt = 0; kt < 3; kt++) {
            int n  = colbase + nt * 8 + gid;
            int j0 = kt * 16 + 2 * tig;
#pragma unroll
            for (int h = 0; h < 2; h++) {
                float w0 = sWf[(j0 + 8 * h    ) * COUT_ + n];
                float w1 = sWf[(j0 + 8 * h + 1) * COUT_ + n];
                B[nt][kt][h] = pack_h_rn(w0, w1);
            }
        }
    }
    __syncthreads();   // W staging dead; sA belongs to pairs now

    const float sg  = sigma[0];
    const float cc2 = -0.72134752f / (sg * sg);   // -0.5*log2(e)/sigma^2

    const uint32_t lmoff = (uint32_t)(lane & 15) * ROWB + (uint32_t)(lane >> 4) * 16;
    const uint32_t sbase = smem_u32(&sA[0][0][0][0]);

    const int ngroups = (npts + 31) >> 5;
    const int g0      = blockIdx.x * 2 + pr;
    const int gstep   = gridDim.x * 2;
    const int barid   = pr + 1;
    const int r       = lane >> 1;        // my staging row
    const int kh      = lane & 1;         // my k-half

    // ---- prefetch first group's x ----
    float xc0 = 0.f, xc1 = 0.f, xc2 = 0.f;
    {
        const int p = (g0 << 5) + j * 16 + r;
        if (g0 < ngroups && p < npts) { xc0 = x[3 * p]; xc1 = x[3 * p + 1]; xc2 = x[3 * p + 2]; }
    }

    int buf = 0;
    for (int grp = g0; grp < ngroups; grp += gstep, buf ^= 1) {
        const int rowbase = grp << 5;

        // ---- phase 1: build my 16-row tile from prefetched x ----
        {
            float a[24];
#pragma unroll
            for (int kk = 0; kk < 8; kk++) {
                const float4 kp = sKP4[8 * kh + kk];
                float dx = xc0 - kp.x, dy = xc1 - kp.y, dz = xc2 - kp.z;
                float d2 = fmaf(dx, dx, fmaf(dy, dy, dz * dz));
                float g  = ex2f(cc2 * d2);
                a[3 * kk] = g * xc0; a[3 * kk + 1] = g * xc1; a[3 * kk + 2] = g * xc2;
            }
            uint32_t hv[12], lv[12];
#pragma unroll
            for (int m = 0; m < 12; m++) {
                float a0 = a[2 * m], a1 = a[2 * m + 1];
                uint32_t hp = pack_h_rn(a0, a1);
                __half2 h2 = *reinterpret_cast<__half2*>(&hp);
                hv[m] = hp;
                lv[m] = pack_h_rn(a0 - __low2float(h2), a1 - __high2float(h2));
            }
            char* rh = &sA[buf][wid][0][0] + r * ROWB + kh * 48;
            char* rl = &sA[buf][wid][1][0] + r * ROWB + kh * 48;
#pragma unroll
            for (int q = 0; q < 3; q++) {
                *reinterpret_cast<uint4*>(rh + q * 16) =
                    make_uint4(hv[4 * q], hv[4 * q + 1], hv[4 * q + 2], hv[4 * q + 3]);
                *reinterpret_cast<uint4*>(rl + q * 16) =
                    make_uint4(lv[4 * q], lv[4 * q + 1], lv[4 * q + 2], lv[4 * q + 3]);
            }
        }

        // ---- prefetch next group's x (overlaps bar + MMA + epilogue) ----
        xc0 = 0.f; xc1 = 0.f; xc2 = 0.f;
        {
            const int gn = grp + gstep;
            const int pn = (gn << 5) + j * 16 + r;
            if (gn < ngroups && pn < npts) {
                xc0 = x[3 * pn]; xc1 = x[3 * pn + 1]; xc2 = x[3 * pn + 2];
            }
        }

        bar_pair(barid);   // both tiles of this group ready

        // ---- phase 2: my 32-col n-half of both 16-row tiles, 2 passes ----
        float acc[2][4][4];
#pragma unroll
        for (int t = 0; t < 2; t++)
#pragma unroll
            for (int nt = 0; nt < 4; nt++)
#pragma unroll
                for (int c = 0; c < 4; c++) acc[t][nt][c] = 0.f;

#pragma unroll
        for (int t = 0; t < 2; t++) {
            const int ownerw = 2 * pr + t;
            const uint32_t aHi = sbase + ((uint32_t)(buf * 8 + ownerw * 2 + 0)) * AWARP + lmoff;
            const uint32_t aLo = sbase + ((uint32_t)(buf * 8 + ownerw * 2 + 1)) * AWARP + lmoff;
#pragma unroll
            for (int kt = 0; kt < 3; kt++) {
                uint32_t ah[4], al[4];
                ldsm_x4(ah, aHi + kt * 32);
                ldsm_x4(al, aLo + kt * 32);
#pragma unroll
                for (int nt = 0; nt < 4; nt++) mma_f16(acc[t][nt], ah, B[nt][kt]);
#pragma unroll
                for (int nt = 0; nt < 4; nt++) mma_f16(acc[t][nt], al, B[nt][kt]);
            }
        }

        // ---- epilogue: butterfly (xor 1) -> float4 -> STG.128 ----
        const bool ev = (tig & 1) == 0;
#pragma unroll
        for (int t = 0; t < 2; t++) {
            const int rowLo = rowbase + 16 * t + gid;
            const int rowHi = rowLo + 8;
#pragma unroll
            for (int ntp = 0; ntp < 2; ntp++) {
                const int ntA = 2 * ntp, ntB = ntA + 1;
                const int col = colbase +
                    (ev ? (16 * ntp + 2 * tig) : (16 * ntp + 8 + 2 * (tig - 1)));
#pragma unroll
                for (int hseg = 0; hseg < 2; hseg++) {
                    float m0 = acc[t][ntA][2 * hseg], m1 = acc[t][ntA][2 * hseg + 1];
                    float b0 = acc[t][ntB][2 * hseg], b1 = acc[t][ntB][2 * hseg + 1];
                    float s0 = ev ? b0 : m0;
                    float s1 = ev ? b1 : m1;
                    float r0 = __shfl_xor_sync(0xFFFFFFFFu, s0, 1);
                    float r1 = __shfl_xor_sync(0xFFFFFFFFu, s1, 1);
                    float4 v;
                    if (ev) v = make_float4(m0, m1, r0, r1);
                    else    v = make_float4(r0, r1, b0, b1);
                    const int row = hseg ? rowHi : rowLo;
                    if (row < npts)
                        *reinterpret_cast<float4*>(out + (size_t)row * COUT_ + col) = v;
                }
            }
        }
        // no second barrier: double buffering + next iteration's bar orders reuse
    }
}

extern "C" void kernel_launch(void* const* d_in, const int* in_sizes, int n_in,
                              void* d_out, int out_size)
{
    const float *x = nullptr, *kp = nullptr, *wt = nullptr, *sg = nullptr;
    int x_elems = 0;
    for (int i = 0; i < n_in; i++) {
        int s = in_sizes[i];
        if (s == 1)                    sg = (const float*)d_in[i];
        else if (s == JDIM)            kp = (const float*)d_in[i];
        else if (s == KP_ * 3 * COUT_) wt = (const float*)d_in[i];
        else { x = (const float*)d_in[i]; x_elems = s; }
    }
    const int npts    = x_elems / 3;
    const int ngroups = (npts + 31) >> 5;
    int grid = 148 * 5;
    int maxg = (ngroups + 1) / 2;
    if (grid > maxg) grid = maxg;

    kpconv_f16p_kernel<<<grid, NTHR>>>(x, kp, wt, sg, (float*)d_out, npts);
}